// round 3
// baseline (speedup 1.0000x reference)
#include <cuda_runtime.h>
#include <cstdint>
#include <cstddef>

// Problem constants
#define BATCH   32
#define DMODEL  2560
#define DINNER  5120
#define NSTATE  16
#define DTRANK  160
#define XDBDIM  192          // DTRANK + 2*NSTATE

// Split-K configs
#define SPLIT_IN   4         // K=2560 -> 640 each          (grid 40*2*4=320)
#define SPLIT_XP   80        // K=5120 -> 64 each           (grid 2*80=160)
#define SPLIT_OUT  14        // K=5120 -> 10x384 + 4x320    (grid 20*14=280)

#define TILE_K 64

// -------- scratch (static device globals; no allocation) ----------
__device__ __align__(256) float g_xT[DMODEL * BATCH];
__device__ __align__(256) float g_part_in[(2 * SPLIT_IN) * BATCH * DINNER];
__device__ __align__(256) float g_convT[DINNER * BATCH];
__device__ __align__(256) float g_gT[DINNER * BATCH];
__device__ __align__(256) float g_part_b[SPLIT_XP * BATCH * XDBDIM];
__device__ __align__(256) float g_xdbT[XDBDIM * BATCH];
__device__ __align__(256) float g_zT[DINNER * BATCH];
__device__ __align__(256) float g_part_c[SPLIT_OUT * BATCH * DMODEL];

// -------- f32x2 helpers (Blackwell packed fp32; PTX-only pattern) ----------
__device__ __forceinline__ unsigned long long fma2(unsigned long long a,
                                                   unsigned long long x,
                                                   unsigned long long c) {
    unsigned long long r;
    asm("fma.rn.f32x2 %0, %1, %2, %3;" : "=l"(r) : "l"(a), "l"(x), "l"(c));
    return r;
}
__device__ __forceinline__ unsigned long long pack2(float v) {
    unsigned long long r;
    asm("mov.b64 %0, {%1, %1};" : "=l"(r) : "f"(v));
    return r;
}
__device__ __forceinline__ float2 unpk(unsigned long long v) {
    float2 r;
    asm("mov.b64 {%0, %1}, %2;" : "=f"(r.x), "=f"(r.y) : "l"(v));
    return r;
}
__device__ __forceinline__ float silu_f(float v) {
    return v / (1.f + __expf(-v));
}

// -------- cp.async helpers ----------
__device__ __forceinline__ uint32_t smem_u32(const void* p) {
    uint32_t r;
    asm("{.reg .u64 t; cvta.to.shared.u64 t, %1; cvt.u32.u64 %0, t;}"
        : "=r"(r) : "l"(p));
    return r;
}
__device__ __forceinline__ void cp_async16(uint32_t dst, const void* src) {
    asm volatile("cp.async.ca.shared.global [%0], [%1], 16;\n" ::"r"(dst), "l"(src));
}
__device__ __forceinline__ void cp_commit() {
    asm volatile("cp.async.commit_group;\n");
}
template <int N>
__device__ __forceinline__ void cp_wait() {
    asm volatile("cp.async.wait_group %0;\n" ::"n"(N));
}

// ===================================================================
// Transpose x (B, DMODEL) -> xT (DMODEL, B) via smem tiles
// ===================================================================
__global__ void __launch_bounds__(256) transpose_x_kernel(const float* __restrict__ x) {
    __shared__ float t[32][33];
    int k0 = blockIdx.x * 32;
    int tx = threadIdx.x, ty = threadIdx.y;
#pragma unroll
    for (int i = 0; i < 4; i++) {
        int b = ty + 8 * i;
        t[b][tx] = x[(size_t)b * DMODEL + k0 + tx];
    }
    __syncthreads();
#pragma unroll
    for (int i = 0; i < 4; i++) {
        int kk = ty + 8 * i;
        g_xT[(size_t)(k0 + kk) * BATCH + tx] = t[tx][kk];
    }
}

// ===================================================================
// Split-K GEMM tile: 256 threads, 128 rows x 32 batch.
// thread = 2 rows x 8 batches.  Weight prefetch ring depth 8 (regs)
// -> 16 LDG.128 in flight per warp.  x tiles double-buffered in smem
// via cp.async.  xT is (K, 32) row-major.  Writes partial to
// partZ[b*M + d].  klen must be a multiple of 64.
// ===================================================================
#define RING 8
__device__ __forceinline__ void gemm_tile3(const float* __restrict__ W,
                                           const float* __restrict__ xT,
                                           float* __restrict__ partZ,
                                           int M, int K, int k0, int klen, int row0) {
    __shared__ __align__(16) float x_s[2][TILE_K * 32];
    const int tid = threadIdx.x;
    const int rg = tid >> 2;   // 0..63 : 2-row group
    const int bg = tid & 3;    // 0..3  : 8-batch group
    const int d0 = row0 + rg * 2;
    int dcl = d0 > M - 2 ? M - 2 : d0;   // clamp for safe loads (store guarded)

    const float4* __restrict__ w0 = (const float4*)(W + (size_t)dcl * K + k0);
    const float4* __restrict__ w1 = (const float4*)(W + (size_t)(dcl + 1) * K + k0);

    const int ntiles = klen / TILE_K;
    const int nkk4 = klen / 4;

    const uint32_t s0 = smem_u32(&x_s[0][0]);
    const uint32_t s1 = smem_u32(&x_s[1][0]);

    // fill x tile 0
    {
        const float* src = xT + (size_t)k0 * BATCH;
        cp_async16(s0 + tid * 16, src + tid * 4);
        cp_async16(s0 + tid * 16 + 4096, src + tid * 4 + 1024);
        cp_commit();
    }

    // weight prefetch ring, depth 8 (kk4 granularity)
    float4 wb0[RING], wb1[RING];
#pragma unroll
    for (int i = 0; i < RING; i++) {
        int j = i < nkk4 ? i : nkk4 - 1;
        wb0[i] = w0[j];
        wb1[i] = w1[j];
    }

    unsigned long long acc[2][4];
#pragma unroll
    for (int r = 0; r < 2; r++)
#pragma unroll
        for (int p = 0; p < 4; p++) acc[r][p] = 0ull;

    for (int t = 0; t < ntiles; t++) {
        if (t + 1 < ntiles) {
            const float* src = xT + (size_t)(k0 + (t + 1) * TILE_K) * BATCH;
            uint32_t dst = ((t + 1) & 1) ? s1 : s0;
            cp_async16(dst + tid * 16, src + tid * 4);
            cp_async16(dst + tid * 16 + 4096, src + tid * 4 + 1024);
            cp_commit();
            cp_wait<1>();
        } else {
            cp_wait<0>();
        }
        __syncthreads();
        const float* xs = x_s[t & 1];
        const int jbase = t * 16;
#pragma unroll
        for (int jj = 0; jj < 16; jj++) {
            float4 wA = wb0[jj & (RING - 1)];
            float4 wB = wb1[jj & (RING - 1)];
            // refill ring slot early (8 kk4 ahead); branchless clamp
            int jn = jbase + jj + RING;
            jn = jn < nkk4 ? jn : nkk4 - 1;
            wb0[jj & (RING - 1)] = w0[jn];
            wb1[jj & (RING - 1)] = w1[jn];

            float wAa[4] = {wA.x, wA.y, wA.z, wA.w};
            float wBa[4] = {wB.x, wB.y, wB.z, wB.w};
#pragma unroll
            for (int kk = 0; kk < 4; kk++) {
                const ulonglong2* xp =
                    (const ulonglong2*)&xs[(jj * 4 + kk) * BATCH + bg * 8];
                ulonglong2 xa = xp[0];
                ulonglong2 xb = xp[1];
                unsigned long long wpA = pack2(wAa[kk]);
                unsigned long long wpB = pack2(wBa[kk]);
                acc[0][0] = fma2(wpA, xa.x, acc[0][0]);
                acc[0][1] = fma2(wpA, xa.y, acc[0][1]);
                acc[0][2] = fma2(wpA, xb.x, acc[0][2]);
                acc[0][3] = fma2(wpA, xb.y, acc[0][3]);
                acc[1][0] = fma2(wpB, xa.x, acc[1][0]);
                acc[1][1] = fma2(wpB, xa.y, acc[1][1]);
                acc[1][2] = fma2(wpB, xb.x, acc[1][2]);
                acc[1][3] = fma2(wpB, xb.y, acc[1][3]);
            }
        }
        __syncthreads();
    }

    if (d0 <= M - 2) {
#pragma unroll
        for (int p = 0; p < 4; p++) {
            float2 a0 = unpk(acc[0][p]);   // row d0,   batches b, b+1
            float2 a1 = unpk(acc[1][p]);   // row d0+1, batches b, b+1
            int b = bg * 8 + 2 * p;
            *(float2*)&partZ[(size_t)b * M + d0] = make_float2(a0.x, a1.x);
            *(float2*)&partZ[(size_t)(b + 1) * M + d0] = make_float2(a0.y, a1.y);
        }
    }
}

// ---- wrappers ----
__global__ void __launch_bounds__(256, 2)
gemm_in_kernel(const float* __restrict__ Wssm, const float* __restrict__ Wmlp) {
    int sel = blockIdx.y;          // 0: ssm, 1: mlp
    int z = blockIdx.z;            // 0..SPLIT_IN-1
    const float* W = sel ? Wmlp : Wssm;
    float* partZ = g_part_in + (size_t)(sel * SPLIT_IN + z) * BATCH * DINNER;
    gemm_tile3(W, g_xT, partZ, DINNER, DMODEL, z * (DMODEL / SPLIT_IN),
               DMODEL / SPLIT_IN, blockIdx.x * 128);
}

__global__ void __launch_bounds__(256, 2)
gemm_xp_kernel(const float* __restrict__ Wxp) {
    int z = blockIdx.z;            // 0..SPLIT_XP-1
    float* partZ = g_part_b + (size_t)z * BATCH * XDBDIM;
    gemm_tile3(Wxp, g_convT, partZ, XDBDIM, DINNER, z * (DINNER / SPLIT_XP),
               DINNER / SPLIT_XP, blockIdx.x * 128);
}

__global__ void __launch_bounds__(256, 2)
gemm_out_kernel(const float* __restrict__ Wout) {
    int z = blockIdx.z;            // 0..SPLIT_OUT-1
    int k0 = z < 10 ? z * 384 : 3840 + (z - 10) * 320;
    int klen = z < 10 ? 384 : 320;
    float* partZ = g_part_c + (size_t)z * BATCH * DMODEL;
    gemm_tile3(Wout, g_zT, partZ, DMODEL, DINNER, k0, klen, blockIdx.x * 128);
}

// ===================================================================
// Epilogue A: sum in_proj partials, depthwise conv + SiLU -> convT,
//             gate SiLU(res) -> gT
// ===================================================================
__global__ void __launch_bounds__(128)
epi_a_kernel(const float* __restrict__ conv_states,
             const float* __restrict__ conv_w,
             const float* __restrict__ conv_b) {
    int d = blockIdx.x * 128 + threadIdx.x;
    float xs[BATCH], res[BATCH];
#pragma unroll
    for (int b = 0; b < BATCH; b++) { xs[b] = 0.f; res[b] = 0.f; }
#pragma unroll
    for (int z = 0; z < SPLIT_IN; z++)
#pragma unroll
        for (int b = 0; b < BATCH; b++)
            xs[b] += g_part_in[(size_t)(z * BATCH + b) * DINNER + d];
#pragma unroll
    for (int z = SPLIT_IN; z < 2 * SPLIT_IN; z++)
#pragma unroll
        for (int b = 0; b < BATCH; b++)
            res[b] += g_part_in[(size_t)(z * BATCH + b) * DINNER + d];

    float cw0 = conv_w[d];
    float cw1 = conv_w[DINNER + d];
    float cw2 = conv_w[2 * DINNER + d];
    float cw3 = conv_w[3 * DINNER + d];
    float cb = conv_b[d];

#pragma unroll
    for (int b4 = 0; b4 < 8; b4++) {
        float cc[4], gw[4];
#pragma unroll
        for (int h = 0; h < 4; h++) {
            int b = b4 * 4 + h;
            float conv = conv_states[(size_t)(1 * BATCH + b) * DINNER + d] * cw0
                       + conv_states[(size_t)(2 * BATCH + b) * DINNER + d] * cw1
                       + conv_states[(size_t)(3 * BATCH + b) * DINNER + d] * cw2
                       + xs[b] * cw3 + cb;
            cc[h] = silu_f(conv);
            gw[h] = silu_f(res[b]);
        }
        *(float4*)&g_convT[(size_t)d * BATCH + b4 * 4] =
            make_float4(cc[0], cc[1], cc[2], cc[3]);
        *(float4*)&g_gT[(size_t)d * BATCH + b4 * 4] =
            make_float4(gw[0], gw[1], gw[2], gw[3]);
    }
}

// ===================================================================
// Epilogue B: sum x_proj partials -> x_dbT (192, 32)
// ===================================================================
__global__ void __launch_bounds__(256) epi_b_kernel() {
    int t = blockIdx.x * 256 + threadIdx.x;   // 0..6143
    int b = t / XDBDIM;
    int r = t - b * XDBDIM;
    float s = 0.f;
#pragma unroll 8
    for (int z = 0; z < SPLIT_XP; z++)
        s += g_part_b[(size_t)(z * BATCH + b) * XDBDIM + r];
    g_xdbT[(size_t)r * BATCH + b] = s;
}

// ===================================================================
// SSM kernel: dt GEMV + softplus + state scan + gate -> zT
// grid (DINNER/128, 8), block 128; blockIdx.y selects 4-batch group
// ===================================================================
#define SSM_BB 4
__global__ void __launch_bounds__(128)
ssm_kernel(const float* __restrict__ W_dt, const float* __restrict__ dt_bias,
           const float* __restrict__ A_log, const float* __restrict__ Dv,
           const float* __restrict__ ssm_state) {
    __shared__ float xdb_s[XDBDIM * SSM_BB];
    const int by = blockIdx.y;
    for (int u = threadIdx.x; u < XDBDIM * SSM_BB; u += 128) {
        int r = u >> 2, bb = u & 3;
        xdb_s[u] = g_xdbT[(size_t)r * BATCH + by * SSM_BB + bb];
    }
    __syncthreads();

    const int d = blockIdx.x * 128 + threadIdx.x;

    float accdt[SSM_BB];
#pragma unroll
    for (int bb = 0; bb < SSM_BB; bb++) accdt[bb] = 0.f;

    const float4* wd = (const float4*)(W_dt + (size_t)d * DTRANK);
#pragma unroll 10
    for (int r4 = 0; r4 < DTRANK / 4; r4++) {
        float4 w = wd[r4];
        float wa[4] = {w.x, w.y, w.z, w.w};
#pragma unroll
        for (int j = 0; j < 4; j++) {
            float4 xv = *(const float4*)&xdb_s[(r4 * 4 + j) * SSM_BB];
            accdt[0] += wa[j] * xv.x;
            accdt[1] += wa[j] * xv.y;
            accdt[2] += wa[j] * xv.z;
            accdt[3] += wa[j] * xv.w;
        }
    }

    float a[NSTATE];
    const float4* al = (const float4*)(A_log + (size_t)d * NSTATE);
#pragma unroll
    for (int n4 = 0; n4 < 4; n4++) {
        float4 v = al[n4];
        a[n4 * 4 + 0] = -__expf(v.x);
        a[n4 * 4 + 1] = -__expf(v.y);
        a[n4 * 4 + 2] = -__expf(v.z);
        a[n4 * 4 + 3] = -__expf(v.w);
    }
    float Dd = Dv[d];
    float bias = dt_bias[d];

    float4 cv4 = *(const float4*)&g_convT[(size_t)d * BATCH + by * SSM_BB];
    float4 gv4 = *(const float4*)&g_gT[(size_t)d * BATCH + by * SSM_BB];
    float cv[SSM_BB] = {cv4.x, cv4.y, cv4.z, cv4.w};
    float gv[SSM_BB] = {gv4.x, gv4.y, gv4.z, gv4.w};
    float zv[SSM_BB];

#pragma unroll
    for (int bb = 0; bb < SSM_BB; bb++) {
        int b = by * SSM_BB + bb;
        float dtv = accdt[bb] + bias;
        float dt = dtv > 20.f ? dtv : log1pf(__expf(dtv));
        float c = cv[bb];
        float y = Dd * c;
        const float4* s4 =
            (const float4*)(ssm_state + ((size_t)b * DINNER + d) * NSTATE);
#pragma unroll
        for (int n4 = 0; n4 < 4; n4++) {
            float4 s = s4[n4];
            float sa[4] = {s.x, s.y, s.z, s.w};
#pragma unroll
            for (int h = 0; h < 4; h++) {
                int n = n4 * 4 + h;
                float dA = __expf(dt * a[n]);
                float hv = sa[h] * dA + dt * xdb_s[(DTRANK + n) * SSM_BB + bb] * c;
                y += hv * xdb_s[(DTRANK + NSTATE + n) * SSM_BB + bb];
            }
        }
        zv[bb] = y * gv[bb];
    }
    *(float4*)&g_zT[(size_t)d * BATCH + by * SSM_BB] =
        make_float4(zv[0], zv[1], zv[2], zv[3]);
}

// ===================================================================
// Epilogue C: sum out_proj partials -> out (B, DMODEL)
// ===================================================================
__global__ void __launch_bounds__(256) epi_c_kernel(float* __restrict__ out) {
    int t = blockIdx.x * 256 + threadIdx.x;   // b*2560+m
    float s = 0.f;
#pragma unroll
    for (int z = 0; z < SPLIT_OUT; z++)
        s += g_part_c[(size_t)z * BATCH * DMODEL + t];
    out[t] = s;
}

// ===================================================================
extern "C" void kernel_launch(void* const* d_in, const int* in_sizes, int n_in,
                              void* d_out, int out_size) {
    const float* x    = (const float*)d_in[0];
    const float* cs   = (const float*)d_in[1];
    const float* cw   = (const float*)d_in[2];
    const float* cb   = (const float*)d_in[3];
    const float* Wssm = (const float*)d_in[4];
    const float* Wmlp = (const float*)d_in[5];
    const float* Wout = (const float*)d_in[6];
    const float* Wxp  = (const float*)d_in[7];
    const float* Wdt  = (const float*)d_in[8];
    const float* dtb  = (const float*)d_in[9];
    const float* Alog = (const float*)d_in[10];
    const float* Dv   = (const float*)d_in[11];
    const float* sst  = (const float*)d_in[12];
    float* out = (float*)d_out;

    transpose_x_kernel<<<DMODEL / 32, dim3(32, 8)>>>(x);
    gemm_in_kernel<<<dim3(DINNER / 128, 2, SPLIT_IN), 256>>>(Wssm, Wmlp);
    epi_a_kernel<<<DINNER / 128, 128>>>(cs, cw, cb);
    gemm_xp_kernel<<<dim3(2, 1, SPLIT_XP), 256>>>(Wxp);
    epi_b_kernel<<<(XDBDIM * BATCH) / 256, 256>>>();
    ssm_kernel<<<dim3(DINNER / 128, 8), 128>>>(Wdt, dtb, Alog, Dv, sst);
    gemm_out_kernel<<<dim3(DMODEL / 128, 1, SPLIT_OUT), 256>>>(Wout);
    epi_c_kernel<<<(BATCH * DMODEL) / 256, 256>>>(out);
}

// round 4
// speedup vs baseline: 1.2234x; 1.2234x over previous
#include <cuda_runtime.h>
#include <cstdint>
#include <cstddef>

// Problem constants
#define BATCH   32
#define DMODEL  2560
#define DINNER  5120
#define NSTATE  16
#define DTRANK  160
#define XDBDIM  192          // DTRANK + 2*NSTATE

// Split-K configs (grid sized for ~444-block capacity at occ 3)
#define SPLIT_IN   5         // K=2560 -> 512 each   (grid 40*2*5 = 400)
#define SPLIT_XP   160       // K=5120 -> 32 each    (grid 2*160  = 320)
#define SPLIT_OUT  20        // K=5120 -> 256 each   (grid 20*20  = 400)

#define CHUNK  32            // k per pipeline stage
#define WROWS  128           // rows per block tile
#define WPAD   36            // padded smem row stride (floats)

// -------- scratch (static device globals; no allocation) ----------
__device__ __align__(256) float g_xT[DMODEL * BATCH];
__device__ __align__(256) float g_part_in[(2 * SPLIT_IN) * BATCH * DINNER];
__device__ __align__(256) float g_convT[DINNER * BATCH];
__device__ __align__(256) float g_gT[DINNER * BATCH];
__device__ __align__(256) float g_part_b[SPLIT_XP * BATCH * XDBDIM];
__device__ __align__(256) float g_xdbT[XDBDIM * BATCH];
__device__ __align__(256) float g_zT[DINNER * BATCH];
__device__ __align__(256) float g_part_c[SPLIT_OUT * BATCH * DMODEL];

// -------- f32x2 helpers (Blackwell packed fp32; PTX-only pattern) ----------
__device__ __forceinline__ unsigned long long fma2(unsigned long long a,
                                                   unsigned long long x,
                                                   unsigned long long c) {
    unsigned long long r;
    asm("fma.rn.f32x2 %0, %1, %2, %3;" : "=l"(r) : "l"(a), "l"(x), "l"(c));
    return r;
}
__device__ __forceinline__ unsigned long long pack2(float v) {
    unsigned long long r;
    asm("mov.b64 %0, {%1, %1};" : "=l"(r) : "f"(v));
    return r;
}
__device__ __forceinline__ float2 unpk(unsigned long long v) {
    float2 r;
    asm("mov.b64 {%0, %1}, %2;" : "=f"(r.x), "=f"(r.y) : "l"(v));
    return r;
}
__device__ __forceinline__ float silu_f(float v) {
    return v / (1.f + __expf(-v));
}

// -------- cp.async helpers ----------
__device__ __forceinline__ uint32_t smem_u32(const void* p) {
    uint32_t r;
    asm("{.reg .u64 t; cvta.to.shared.u64 t, %1; cvt.u32.u64 %0, t;}"
        : "=r"(r) : "l"(p));
    return r;
}
__device__ __forceinline__ void cp_async16(uint32_t dst, const void* src) {
    asm volatile("cp.async.ca.shared.global [%0], [%1], 16;\n" ::"r"(dst), "l"(src));
}
__device__ __forceinline__ void cp_commit() {
    asm volatile("cp.async.commit_group;\n");
}
template <int N>
__device__ __forceinline__ void cp_wait() {
    asm volatile("cp.async.wait_group %0;\n" ::"n"(N));
}

// ===================================================================
// Transpose x (B, DMODEL) -> xT (DMODEL, B) via smem tiles
// ===================================================================
__global__ void __launch_bounds__(256) transpose_x_kernel(const float* __restrict__ x) {
    __shared__ float t[32][33];
    int k0 = blockIdx.x * 32;
    int tx = threadIdx.x, ty = threadIdx.y;
#pragma unroll
    for (int i = 0; i < 4; i++) {
        int b = ty + 8 * i;
        t[b][tx] = x[(size_t)b * DMODEL + k0 + tx];
    }
    __syncthreads();
#pragma unroll
    for (int i = 0; i < 4; i++) {
        int kk = ty + 8 * i;
        g_xT[(size_t)(k0 + kk) * BATCH + tx] = t[tx][kk];
    }
}

// ===================================================================
// Split-K GEMM tile: 256 threads, 128 rows x 32 batch.
// Weights AND activations staged through smem via coalesced cp.async
// (double-buffered, 32-k chunks).  Compute reads both via broadcast
// LDS.  Thread = 2 rows x 8 batches, f32x2 accumulators.
// xT is (K, 32) row-major.  Writes partial to partZ[b*M + d].
// klen must be a multiple of 32.
// ===================================================================
__device__ __forceinline__ void gemm_tile4(const float* __restrict__ W,
                                           const float* __restrict__ xT,
                                           float* __restrict__ partZ,
                                           int M, int K, int k0, int klen, int row0) {
    __shared__ __align__(16) float w_s[2][WROWS * WPAD];
    __shared__ __align__(16) float x_s[2][CHUNK * WPAD];

    const int tid = threadIdx.x;
    const int rg = tid >> 2;   // 0..63 : 2-row group
    const int bg = tid & 3;    // 0..3  : 8-batch group
    const int d0 = row0 + rg * 2;

    const int nchunk = klen / CHUNK;

    const uint32_t ws0 = smem_u32(&w_s[0][0]);
    const uint32_t ws1 = smem_u32(&w_s[1][0]);
    const uint32_t xs0 = smem_u32(&x_s[0][0]);
    const uint32_t xs1 = smem_u32(&x_s[1][0]);

    // fill chunk c into stage s
    auto fill = [&](int s, int c) {
        const int kc = k0 + c * CHUNK;
        uint32_t wd = s ? ws1 : ws0;
        uint32_t xd = s ? xs1 : xs0;
        // weights: 128 rows x 128B ; piece p -> row p>>3, 16B-off p&7
#pragma unroll
        for (int i = 0; i < 4; i++) {
            int p = tid + 256 * i;
            int r = p >> 3, off = p & 7;
            cp_async16(wd + (uint32_t)(r * WPAD + off * 4) * 4,
                       W + (size_t)(row0 + r) * K + kc + off * 4);
        }
        // x: 32 k-rows x 128B ; piece tid -> k tid>>3, off tid&7
        {
            int k = tid >> 3, off = tid & 7;
            cp_async16(xd + (uint32_t)(k * WPAD + off * 4) * 4,
                       xT + (size_t)(kc + k) * BATCH + off * 4);
        }
        cp_commit();
    };

    fill(0, 0);

    unsigned long long acc[2][4];
#pragma unroll
    for (int r = 0; r < 2; r++)
#pragma unroll
        for (int p = 0; p < 4; p++) acc[r][p] = 0ull;

    for (int c = 0; c < nchunk; c++) {
        if (c + 1 < nchunk) {
            fill((c + 1) & 1, c + 1);
            cp_wait<1>();
        } else {
            cp_wait<0>();
        }
        __syncthreads();
        const float* ws = w_s[c & 1];
        const float* xs = x_s[c & 1];
#pragma unroll
        for (int kk4 = 0; kk4 < CHUNK / 4; kk4++) {
            float4 wA = *(const float4*)&ws[(2 * rg) * WPAD + kk4 * 4];
            float4 wB = *(const float4*)&ws[(2 * rg + 1) * WPAD + kk4 * 4];
            float wAa[4] = {wA.x, wA.y, wA.z, wA.w};
            float wBa[4] = {wB.x, wB.y, wB.z, wB.w};
#pragma unroll
            for (int kk = 0; kk < 4; kk++) {
                const ulonglong2* xp =
                    (const ulonglong2*)&xs[(kk4 * 4 + kk) * WPAD + bg * 8];
                ulonglong2 xa = xp[0];
                ulonglong2 xb = xp[1];
                unsigned long long wpA = pack2(wAa[kk]);
                unsigned long long wpB = pack2(wBa[kk]);
                acc[0][0] = fma2(wpA, xa.x, acc[0][0]);
                acc[0][1] = fma2(wpA, xa.y, acc[0][1]);
                acc[0][2] = fma2(wpA, xb.x, acc[0][2]);
                acc[0][3] = fma2(wpA, xb.y, acc[0][3]);
                acc[1][0] = fma2(wpB, xa.x, acc[1][0]);
                acc[1][1] = fma2(wpB, xa.y, acc[1][1]);
                acc[1][2] = fma2(wpB, xb.x, acc[1][2]);
                acc[1][3] = fma2(wpB, xb.y, acc[1][3]);
            }
        }
        __syncthreads();
    }

#pragma unroll
    for (int p = 0; p < 4; p++) {
        float2 a0 = unpk(acc[0][p]);   // row d0,   batches b, b+1
        float2 a1 = unpk(acc[1][p]);   // row d0+1, batches b, b+1
        int b = bg * 8 + 2 * p;
        *(float2*)&partZ[(size_t)b * M + d0] = make_float2(a0.x, a1.x);
        *(float2*)&partZ[(size_t)(b + 1) * M + d0] = make_float2(a0.y, a1.y);
    }
}

// ---- wrappers ----
__global__ void __launch_bounds__(256, 3)
gemm_in_kernel(const float* __restrict__ Wssm, const float* __restrict__ Wmlp) {
    int sel = blockIdx.y;          // 0: ssm, 1: mlp
    int z = blockIdx.z;            // 0..SPLIT_IN-1
    const float* W = sel ? Wmlp : Wssm;
    float* partZ = g_part_in + (size_t)(sel * SPLIT_IN + z) * BATCH * DINNER;
    gemm_tile4(W, g_xT, partZ, DINNER, DMODEL, z * (DMODEL / SPLIT_IN),
               DMODEL / SPLIT_IN, blockIdx.x * WROWS);
}

__global__ void __launch_bounds__(256, 3)
gemm_xp_kernel(const float* __restrict__ Wxp) {
    int z = blockIdx.z;            // 0..SPLIT_XP-1
    float* partZ = g_part_b + (size_t)z * BATCH * XDBDIM;
    // M=192: block0 rows 0..127, block1 rows 64..191 (overlap writes identical)
    gemm_tile4(Wxp, g_convT, partZ, XDBDIM, DINNER, z * (DINNER / SPLIT_XP),
               DINNER / SPLIT_XP, blockIdx.x * 64);
}

__global__ void __launch_bounds__(256, 3)
gemm_out_kernel(const float* __restrict__ Wout) {
    int z = blockIdx.z;            // 0..SPLIT_OUT-1
    float* partZ = g_part_c + (size_t)z * BATCH * DMODEL;
    gemm_tile4(Wout, g_zT, partZ, DMODEL, DINNER, z * (DINNER / SPLIT_OUT),
               DINNER / SPLIT_OUT, blockIdx.x * WROWS);
}

// ===================================================================
// Epilogue A: sum in_proj partials, depthwise conv + SiLU -> convT,
//             gate SiLU(res) -> gT
// ===================================================================
__global__ void __launch_bounds__(128)
epi_a_kernel(const float* __restrict__ conv_states,
             const float* __restrict__ conv_w,
             const float* __restrict__ conv_b) {
    int d = blockIdx.x * 128 + threadIdx.x;
    float xs[BATCH], res[BATCH];
#pragma unroll
    for (int b = 0; b < BATCH; b++) { xs[b] = 0.f; res[b] = 0.f; }
#pragma unroll
    for (int z = 0; z < SPLIT_IN; z++)
#pragma unroll
        for (int b = 0; b < BATCH; b++)
            xs[b] += g_part_in[(size_t)(z * BATCH + b) * DINNER + d];
#pragma unroll
    for (int z = SPLIT_IN; z < 2 * SPLIT_IN; z++)
#pragma unroll
        for (int b = 0; b < BATCH; b++)
            res[b] += g_part_in[(size_t)(z * BATCH + b) * DINNER + d];

    float cw0 = conv_w[d];
    float cw1 = conv_w[DINNER + d];
    float cw2 = conv_w[2 * DINNER + d];
    float cw3 = conv_w[3 * DINNER + d];
    float cb = conv_b[d];

#pragma unroll
    for (int b4 = 0; b4 < 8; b4++) {
        float cc[4], gw[4];
#pragma unroll
        for (int h = 0; h < 4; h++) {
            int b = b4 * 4 + h;
            float conv = conv_states[(size_t)(1 * BATCH + b) * DINNER + d] * cw0
                       + conv_states[(size_t)(2 * BATCH + b) * DINNER + d] * cw1
                       + conv_states[(size_t)(3 * BATCH + b) * DINNER + d] * cw2
                       + xs[b] * cw3 + cb;
            cc[h] = silu_f(conv);
            gw[h] = silu_f(res[b]);
        }
        *(float4*)&g_convT[(size_t)d * BATCH + b4 * 4] =
            make_float4(cc[0], cc[1], cc[2], cc[3]);
        *(float4*)&g_gT[(size_t)d * BATCH + b4 * 4] =
            make_float4(gw[0], gw[1], gw[2], gw[3]);
    }
}

// ===================================================================
// Epilogue B: sum x_proj partials -> x_dbT (192, 32)
// ===================================================================
__global__ void __launch_bounds__(256) epi_b_kernel() {
    int t = blockIdx.x * 256 + threadIdx.x;   // 0..6143
    int b = t / XDBDIM;
    int r = t - b * XDBDIM;
    float s = 0.f;
#pragma unroll 8
    for (int z = 0; z < SPLIT_XP; z++)
        s += g_part_b[(size_t)(z * BATCH + b) * XDBDIM + r];
    g_xdbT[(size_t)r * BATCH + b] = s;
}

// ===================================================================
// SSM kernel: dt GEMV + softplus + state scan + gate -> zT
// grid (DINNER/128, 8), block 128; blockIdx.y selects 4-batch group
// ===================================================================
#define SSM_BB 4
__global__ void __launch_bounds__(128)
ssm_kernel(const float* __restrict__ W_dt, const float* __restrict__ dt_bias,
           const float* __restrict__ A_log, const float* __restrict__ Dv,
           const float* __restrict__ ssm_state) {
    __shared__ float xdb_s[XDBDIM * SSM_BB];
    const int by = blockIdx.y;
    for (int u = threadIdx.x; u < XDBDIM * SSM_BB; u += 128) {
        int r = u >> 2, bb = u & 3;
        xdb_s[u] = g_xdbT[(size_t)r * BATCH + by * SSM_BB + bb];
    }
    __syncthreads();

    const int d = blockIdx.x * 128 + threadIdx.x;

    float accdt[SSM_BB];
#pragma unroll
    for (int bb = 0; bb < SSM_BB; bb++) accdt[bb] = 0.f;

    const float4* wd = (const float4*)(W_dt + (size_t)d * DTRANK);
#pragma unroll 10
    for (int r4 = 0; r4 < DTRANK / 4; r4++) {
        float4 w = wd[r4];
        float wa[4] = {w.x, w.y, w.z, w.w};
#pragma unroll
        for (int j = 0; j < 4; j++) {
            float4 xv = *(const float4*)&xdb_s[(r4 * 4 + j) * SSM_BB];
            accdt[0] += wa[j] * xv.x;
            accdt[1] += wa[j] * xv.y;
            accdt[2] += wa[j] * xv.z;
            accdt[3] += wa[j] * xv.w;
        }
    }

    float a[NSTATE];
    const float4* al = (const float4*)(A_log + (size_t)d * NSTATE);
#pragma unroll
    for (int n4 = 0; n4 < 4; n4++) {
        float4 v = al[n4];
        a[n4 * 4 + 0] = -__expf(v.x);
        a[n4 * 4 + 1] = -__expf(v.y);
        a[n4 * 4 + 2] = -__expf(v.z);
        a[n4 * 4 + 3] = -__expf(v.w);
    }
    float Dd = Dv[d];
    float bias = dt_bias[d];

    float4 cv4 = *(const float4*)&g_convT[(size_t)d * BATCH + by * SSM_BB];
    float4 gv4 = *(const float4*)&g_gT[(size_t)d * BATCH + by * SSM_BB];
    float cv[SSM_BB] = {cv4.x, cv4.y, cv4.z, cv4.w};
    float gv[SSM_BB] = {gv4.x, gv4.y, gv4.z, gv4.w};
    float zv[SSM_BB];

#pragma unroll
    for (int bb = 0; bb < SSM_BB; bb++) {
        int b = by * SSM_BB + bb;
        float dtv = accdt[bb] + bias;
        float dt = dtv > 20.f ? dtv : log1pf(__expf(dtv));
        float c = cv[bb];
        float y = Dd * c;
        const float4* s4 =
            (const float4*)(ssm_state + ((size_t)b * DINNER + d) * NSTATE);
#pragma unroll
        for (int n4 = 0; n4 < 4; n4++) {
            float4 s = s4[n4];
            float sa[4] = {s.x, s.y, s.z, s.w};
#pragma unroll
            for (int h = 0; h < 4; h++) {
                int n = n4 * 4 + h;
                float dA = __expf(dt * a[n]);
                float hv = sa[h] * dA + dt * xdb_s[(DTRANK + n) * SSM_BB + bb] * c;
                y += hv * xdb_s[(DTRANK + NSTATE + n) * SSM_BB + bb];
            }
        }
        zv[bb] = y * gv[bb];
    }
    *(float4*)&g_zT[(size_t)d * BATCH + by * SSM_BB] =
        make_float4(zv[0], zv[1], zv[2], zv[3]);
}

// ===================================================================
// Epilogue C: sum out_proj partials -> out (B, DMODEL)
// ===================================================================
__global__ void __launch_bounds__(256) epi_c_kernel(float* __restrict__ out) {
    int t = blockIdx.x * 256 + threadIdx.x;   // b*2560+m
    float s = 0.f;
#pragma unroll
    for (int z = 0; z < SPLIT_OUT; z++)
        s += g_part_c[(size_t)z * BATCH * DMODEL + t];
    out[t] = s;
}

// ===================================================================
extern "C" void kernel_launch(void* const* d_in, const int* in_sizes, int n_in,
                              void* d_out, int out_size) {
    const float* x    = (const float*)d_in[0];
    const float* cs   = (const float*)d_in[1];
    const float* cw   = (const float*)d_in[2];
    const float* cb   = (const float*)d_in[3];
    const float* Wssm = (const float*)d_in[4];
    const float* Wmlp = (const float*)d_in[5];
    const float* Wout = (const float*)d_in[6];
    const float* Wxp  = (const float*)d_in[7];
    const float* Wdt  = (const float*)d_in[8];
    const float* dtb  = (const float*)d_in[9];
    const float* Alog = (const float*)d_in[10];
    const float* Dv   = (const float*)d_in[11];
    const float* sst  = (const float*)d_in[12];
    float* out = (float*)d_out;

    transpose_x_kernel<<<DMODEL / 32, dim3(32, 8)>>>(x);
    gemm_in_kernel<<<dim3(DINNER / WROWS, 2, SPLIT_IN), 256>>>(Wssm, Wmlp);
    epi_a_kernel<<<DINNER / 128, 128>>>(cs, cw, cb);
    gemm_xp_kernel<<<dim3(2, 1, SPLIT_XP), 256>>>(Wxp);
    epi_b_kernel<<<(XDBDIM * BATCH) / 256, 256>>>();
    ssm_kernel<<<dim3(DINNER / 128, 8), 128>>>(Wdt, dtb, Alog, Dv, sst);
    gemm_out_kernel<<<dim3(DMODEL / WROWS, 1, SPLIT_OUT), 256>>>(Wout);
    epi_c_kernel<<<(BATCH * DMODEL) / 256, 256>>>(out);
}

// round 5
// speedup vs baseline: 1.3997x; 1.1441x over previous
#include <cuda_runtime.h>
#include <cstdint>
#include <cstddef>

// Problem constants
#define BATCH   32
#define DMODEL  2560
#define DINNER  5120
#define NSTATE  16
#define DTRANK  160
#define XDBDIM  192          // DTRANK + 2*NSTATE

// Split-K configs (GEMM block = 256 rows x 32 batch, occ 4 -> 592 slots)
#define SPLIT_IN   10        // K=2560 -> 256 each   (grid 20*2*10 = 400)
#define SPLIT_XP   80        // K=5120 -> 64 each    (grid 80)
#define SPLIT_OUT  40        // K=5120 -> 128 each   (grid 10*40 = 400)

#define CHUNK  16            // k per pipeline stage
#define TROWS  256           // rows per block tile

// -------- scratch (static device globals; no allocation) ----------
// partial layouts: [z][d][b]  (b fastest, 32 wide)
__device__ __align__(256) float g_xT[DMODEL * BATCH];
__device__ __align__(256) float g_part_in[(2 * SPLIT_IN) * DINNER * BATCH];
__device__ __align__(256) float g_convT[DINNER * BATCH];
__device__ __align__(256) float g_gT[DINNER * BATCH];
__device__ __align__(256) float g_part_b[SPLIT_XP * XDBDIM * BATCH];
__device__ __align__(256) float g_xdbT[XDBDIM * BATCH];
__device__ __align__(256) float g_zT[DINNER * BATCH];
__device__ __align__(256) float g_part_c[SPLIT_OUT * DMODEL * BATCH];

// -------- f32x2 helpers (Blackwell packed fp32; PTX-only pattern) ----------
__device__ __forceinline__ unsigned long long fma2(unsigned long long a,
                                                   unsigned long long x,
                                                   unsigned long long c) {
    unsigned long long r;
    asm("fma.rn.f32x2 %0, %1, %2, %3;" : "=l"(r) : "l"(a), "l"(x), "l"(c));
    return r;
}
__device__ __forceinline__ unsigned long long pack2(float v) {
    unsigned long long r;
    asm("mov.b64 %0, {%1, %1};" : "=l"(r) : "f"(v));
    return r;
}
__device__ __forceinline__ float2 unpk(unsigned long long v) {
    float2 r;
    asm("mov.b64 {%0, %1}, %2;" : "=f"(r.x), "=f"(r.y) : "l"(v));
    return r;
}
__device__ __forceinline__ float silu_f(float v) {
    return v / (1.f + __expf(-v));
}

// -------- cp.async helpers ----------
__device__ __forceinline__ uint32_t smem_u32(const void* p) {
    uint32_t r;
    asm("{.reg .u64 t; cvta.to.shared.u64 t, %1; cvt.u32.u64 %0, t;}"
        : "=r"(r) : "l"(p));
    return r;
}
__device__ __forceinline__ void cp_async16(uint32_t dst, const void* src) {
    asm volatile("cp.async.ca.shared.global [%0], [%1], 16;\n" ::"r"(dst), "l"(src));
}
__device__ __forceinline__ void cp_commit() {
    asm volatile("cp.async.commit_group;\n");
}
template <int N>
__device__ __forceinline__ void cp_wait() {
    asm volatile("cp.async.wait_group %0;\n" ::"n"(N));
}

// ===================================================================
// Transpose x (B, DMODEL) -> xT (DMODEL, B) via smem tiles
// ===================================================================
__global__ void __launch_bounds__(256) transpose_x_kernel(const float* __restrict__ x) {
    __shared__ float t[32][33];
    int k0 = blockIdx.x * 32;
    int tx = threadIdx.x, ty = threadIdx.y;
#pragma unroll
    for (int i = 0; i < 4; i++) {
        int b = ty + 8 * i;
        t[b][tx] = x[(size_t)b * DMODEL + k0 + tx];
    }
    __syncthreads();
#pragma unroll
    for (int i = 0; i < 4; i++) {
        int kk = ty + 8 * i;
        g_xT[(size_t)(k0 + kk) * BATCH + tx] = t[tx][kk];
    }
}

// ===================================================================
// Split-K GEMM tile: 128 threads, 256 rows x 32 batch.
// Thread: 8 rows (strided 32) x 8 batches -> balanced LDS/FMA.
// Weights + x staged via cp.async (double buffer, 16-k chunks).
// xT is (K, 32) row-major. Writes partial to partZ[d*32 + b].
// klen must be a multiple of 16.
// ===================================================================
__device__ __forceinline__ void gemm_tile5(const float* __restrict__ W,
                                           const float* __restrict__ xT,
                                           float* __restrict__ partZ,
                                           int M, int K, int k0, int klen, int row0) {
    __shared__ __align__(16) float w_s[2][TROWS * CHUNK];   // 16 KB per stage
    __shared__ __align__(16) float x_s[2][CHUNK * BATCH];   //  2 KB per stage

    const int tid = threadIdx.x;
    const int rg = tid >> 2;   // 0..31 : base row in tile
    const int bg = tid & 3;    // 0..3  : 8-batch group

    const int nchunk = klen / CHUNK;

    const uint32_t ws0 = smem_u32(&w_s[0][0]);
    const uint32_t ws1 = smem_u32(&w_s[1][0]);
    const uint32_t xs0 = smem_u32(&x_s[0][0]);
    const uint32_t xs1 = smem_u32(&x_s[1][0]);

    // fill chunk c into stage s
    auto fill = [&](int s, int c) {
        const int kc = k0 + c * CHUNK;
        uint32_t wd = s ? ws1 : ws0;
        uint32_t xd = s ? xs1 : xs0;
        // weights: 256 rows x 64B ; piece p -> row p>>2, 16B-off p&3
#pragma unroll
        for (int i = 0; i < 8; i++) {
            int p = tid + 128 * i;
            int r = p >> 2, off = p & 3;
            int gr = row0 + r;
            gr = gr < M ? gr : M - 1;          // clamp (xp tail rows)
            cp_async16(wd + (uint32_t)(r * CHUNK + off * 4) * 4,
                       W + (size_t)gr * K + kc + off * 4);
        }
        // x: 16 k-rows x 128B ; tid -> k tid>>3, off tid&7
        {
            int k = tid >> 3, off = tid & 7;
            cp_async16(xd + (uint32_t)(k * BATCH + off * 4) * 4,
                       xT + (size_t)(kc + k) * BATCH + off * 4);
        }
        cp_commit();
    };

    fill(0, 0);

    unsigned long long acc[8][4];
#pragma unroll
    for (int i = 0; i < 8; i++)
#pragma unroll
        for (int p = 0; p < 4; p++) acc[i][p] = 0ull;

    for (int c = 0; c < nchunk; c++) {
        if (c + 1 < nchunk) {
            fill((c + 1) & 1, c + 1);
            cp_wait<1>();
        } else {
            cp_wait<0>();
        }
        __syncthreads();
        const float* ws = w_s[c & 1];
        const float* xs = x_s[c & 1];
#pragma unroll
        for (int kk4 = 0; kk4 < CHUNK / 4; kk4++) {
            // load x for this kk4: 4 k-rows x 8 batches
            unsigned long long xr[4][4];
#pragma unroll
            for (int kk = 0; kk < 4; kk++) {
                const ulonglong2* xp =
                    (const ulonglong2*)&xs[(kk4 * 4 + kk) * BATCH + bg * 8];
                ulonglong2 a = xp[0];
                ulonglong2 b = xp[1];
                xr[kk][0] = a.x; xr[kk][1] = a.y;
                xr[kk][2] = b.x; xr[kk][3] = b.y;
            }
#pragma unroll
            for (int i = 0; i < 8; i++) {
                float4 w = *(const float4*)&ws[(rg + 32 * i) * CHUNK + kk4 * 4];
                float wa[4] = {w.x, w.y, w.z, w.w};
#pragma unroll
                for (int kk = 0; kk < 4; kk++) {
                    unsigned long long wp = pack2(wa[kk]);
                    acc[i][0] = fma2(wp, xr[kk][0], acc[i][0]);
                    acc[i][1] = fma2(wp, xr[kk][1], acc[i][1]);
                    acc[i][2] = fma2(wp, xr[kk][2], acc[i][2]);
                    acc[i][3] = fma2(wp, xr[kk][3], acc[i][3]);
                }
            }
        }
        __syncthreads();
    }

    // store: partZ[d*32 + b], vectorized over b
#pragma unroll
    for (int i = 0; i < 8; i++) {
        int d = row0 + rg + 32 * i;
        if (d < M) {
            float2 a0 = unpk(acc[i][0]);
            float2 a1 = unpk(acc[i][1]);
            float2 a2 = unpk(acc[i][2]);
            float2 a3 = unpk(acc[i][3]);
            float* dst = partZ + (size_t)d * BATCH + bg * 8;
            *(float4*)(dst)     = make_float4(a0.x, a0.y, a1.x, a1.y);
            *(float4*)(dst + 4) = make_float4(a2.x, a2.y, a3.x, a3.y);
        }
    }
}

// ---- wrappers ----
__global__ void __launch_bounds__(128, 4)
gemm_in_kernel(const float* __restrict__ Wssm, const float* __restrict__ Wmlp) {
    int sel = blockIdx.y;          // 0: ssm, 1: mlp
    int z = blockIdx.z;            // 0..SPLIT_IN-1
    const float* W = sel ? Wmlp : Wssm;
    float* partZ = g_part_in + (size_t)(sel * SPLIT_IN + z) * DINNER * BATCH;
    gemm_tile5(W, g_xT, partZ, DINNER, DMODEL, z * (DMODEL / SPLIT_IN),
               DMODEL / SPLIT_IN, blockIdx.x * TROWS);
}

__global__ void __launch_bounds__(128, 4)
gemm_xp_kernel(const float* __restrict__ Wxp) {
    int z = blockIdx.z;            // 0..SPLIT_XP-1
    float* partZ = g_part_b + (size_t)z * XDBDIM * BATCH;
    gemm_tile5(Wxp, g_convT, partZ, XDBDIM, DINNER, z * (DINNER / SPLIT_XP),
               DINNER / SPLIT_XP, 0);
}

__global__ void __launch_bounds__(128, 4)
gemm_out_kernel(const float* __restrict__ Wout) {
    int z = blockIdx.z;            // 0..SPLIT_OUT-1
    float* partZ = g_part_c + (size_t)z * DMODEL * BATCH;
    gemm_tile5(Wout, g_zT, partZ, DMODEL, DINNER, z * (DINNER / SPLIT_OUT),
               DINNER / SPLIT_OUT, blockIdx.x * TROWS);
}

// ===================================================================
// Epilogue A: sum in_proj partials, depthwise conv + SiLU -> convT,
//             gate SiLU(res) -> gT       (partials are [z][d][b])
// ===================================================================
__global__ void __launch_bounds__(128)
epi_a_kernel(const float* __restrict__ conv_states,
             const float* __restrict__ conv_w,
             const float* __restrict__ conv_b) {
    int d = blockIdx.x * 128 + threadIdx.x;
    float xs[BATCH], res[BATCH];
#pragma unroll
    for (int b = 0; b < BATCH; b++) { xs[b] = 0.f; res[b] = 0.f; }
#pragma unroll
    for (int z = 0; z < SPLIT_IN; z++) {
        const float4* p =
            (const float4*)(g_part_in + ((size_t)z * DINNER + d) * BATCH);
#pragma unroll
        for (int q = 0; q < 8; q++) {
            float4 v = p[q];
            xs[q * 4 + 0] += v.x; xs[q * 4 + 1] += v.y;
            xs[q * 4 + 2] += v.z; xs[q * 4 + 3] += v.w;
        }
    }
#pragma unroll
    for (int z = SPLIT_IN; z < 2 * SPLIT_IN; z++) {
        const float4* p =
            (const float4*)(g_part_in + ((size_t)z * DINNER + d) * BATCH);
#pragma unroll
        for (int q = 0; q < 8; q++) {
            float4 v = p[q];
            res[q * 4 + 0] += v.x; res[q * 4 + 1] += v.y;
            res[q * 4 + 2] += v.z; res[q * 4 + 3] += v.w;
        }
    }

    float cw0 = conv_w[d];
    float cw1 = conv_w[DINNER + d];
    float cw2 = conv_w[2 * DINNER + d];
    float cw3 = conv_w[3 * DINNER + d];
    float cb = conv_b[d];

#pragma unroll
    for (int b4 = 0; b4 < 8; b4++) {
        float cc[4], gw[4];
#pragma unroll
        for (int h = 0; h < 4; h++) {
            int b = b4 * 4 + h;
            float conv = conv_states[(size_t)(1 * BATCH + b) * DINNER + d] * cw0
                       + conv_states[(size_t)(2 * BATCH + b) * DINNER + d] * cw1
                       + conv_states[(size_t)(3 * BATCH + b) * DINNER + d] * cw2
                       + xs[b] * cw3 + cb;
            cc[h] = silu_f(conv);
            gw[h] = silu_f(res[b]);
        }
        *(float4*)&g_convT[(size_t)d * BATCH + b4 * 4] =
            make_float4(cc[0], cc[1], cc[2], cc[3]);
        *(float4*)&g_gT[(size_t)d * BATCH + b4 * 4] =
            make_float4(gw[0], gw[1], gw[2], gw[3]);
    }
}

// ===================================================================
// Epilogue B: sum x_proj partials -> x_dbT (192, 32)   ([z][r][b])
// ===================================================================
__global__ void __launch_bounds__(256) epi_b_kernel() {
    int t = blockIdx.x * 256 + threadIdx.x;   // 0..6143 = r*32+b
    float s = 0.f;
#pragma unroll 8
    for (int z = 0; z < SPLIT_XP; z++)
        s += g_part_b[(size_t)z * XDBDIM * BATCH + t];
    g_xdbT[t] = s;
}

// ===================================================================
// SSM kernel: dt GEMV + softplus + state scan + gate -> zT
// grid (DINNER/128, 8), block 128; blockIdx.y selects 4-batch group
// ===================================================================
#define SSM_BB 4
__global__ void __launch_bounds__(128)
ssm_kernel(const float* __restrict__ W_dt, const float* __restrict__ dt_bias,
           const float* __restrict__ A_log, const float* __restrict__ Dv,
           const float* __restrict__ ssm_state) {
    __shared__ float xdb_s[XDBDIM * SSM_BB];
    const int by = blockIdx.y;
    for (int u = threadIdx.x; u < XDBDIM * SSM_BB; u += 128) {
        int r = u >> 2, bb = u & 3;
        xdb_s[u] = g_xdbT[(size_t)r * BATCH + by * SSM_BB + bb];
    }
    __syncthreads();

    const int d = blockIdx.x * 128 + threadIdx.x;

    float accdt[SSM_BB];
#pragma unroll
    for (int bb = 0; bb < SSM_BB; bb++) accdt[bb] = 0.f;

    const float4* wd = (const float4*)(W_dt + (size_t)d * DTRANK);
#pragma unroll 10
    for (int r4 = 0; r4 < DTRANK / 4; r4++) {
        float4 w = wd[r4];
        float wa[4] = {w.x, w.y, w.z, w.w};
#pragma unroll
        for (int j = 0; j < 4; j++) {
            float4 xv = *(const float4*)&xdb_s[(r4 * 4 + j) * SSM_BB];
            accdt[0] += wa[j] * xv.x;
            accdt[1] += wa[j] * xv.y;
            accdt[2] += wa[j] * xv.z;
            accdt[3] += wa[j] * xv.w;
        }
    }

    float a[NSTATE];
    const float4* al = (const float4*)(A_log + (size_t)d * NSTATE);
#pragma unroll
    for (int n4 = 0; n4 < 4; n4++) {
        float4 v = al[n4];
        a[n4 * 4 + 0] = -__expf(v.x);
        a[n4 * 4 + 1] = -__expf(v.y);
        a[n4 * 4 + 2] = -__expf(v.z);
        a[n4 * 4 + 3] = -__expf(v.w);
    }
    float Dd = Dv[d];
    float bias = dt_bias[d];

    float4 cv4 = *(const float4*)&g_convT[(size_t)d * BATCH + by * SSM_BB];
    float4 gv4 = *(const float4*)&g_gT[(size_t)d * BATCH + by * SSM_BB];
    float cv[SSM_BB] = {cv4.x, cv4.y, cv4.z, cv4.w};
    float gv[SSM_BB] = {gv4.x, gv4.y, gv4.z, gv4.w};
    float zv[SSM_BB];

#pragma unroll
    for (int bb = 0; bb < SSM_BB; bb++) {
        int b = by * SSM_BB + bb;
        float dtv = accdt[bb] + bias;
        float dt = dtv > 20.f ? dtv : log1pf(__expf(dtv));
        float c = cv[bb];
        float y = Dd * c;
        const float4* s4 =
            (const float4*)(ssm_state + ((size_t)b * DINNER + d) * NSTATE);
#pragma unroll
        for (int n4 = 0; n4 < 4; n4++) {
            float4 s = s4[n4];
            float sa[4] = {s.x, s.y, s.z, s.w};
#pragma unroll
            for (int h = 0; h < 4; h++) {
                int n = n4 * 4 + h;
                float dA = __expf(dt * a[n]);
                float hv = sa[h] * dA + dt * xdb_s[(DTRANK + n) * SSM_BB + bb] * c;
                y += hv * xdb_s[(DTRANK + NSTATE + n) * SSM_BB + bb];
            }
        }
        zv[bb] = y * gv[bb];
    }
    *(float4*)&g_zT[(size_t)d * BATCH + by * SSM_BB] =
        make_float4(zv[0], zv[1], zv[2], zv[3]);
}

// ===================================================================
// Epilogue C: sum out_proj partials [z][m][b] -> out (B, DMODEL)
// block 256, grid DMODEL/64; smem transpose
// ===================================================================
__global__ void __launch_bounds__(256) epi_c_kernel(float* __restrict__ out) {
    __shared__ float tile[64][33];
    int m0 = blockIdx.x * 64;
    int tid = threadIdx.x;
    {
        int ml = tid >> 2;        // 0..63
        int bq = tid & 3;         // 0..3 (8 b's)
        float4 s0 = make_float4(0.f, 0.f, 0.f, 0.f);
        float4 s1 = make_float4(0.f, 0.f, 0.f, 0.f);
#pragma unroll
        for (int z = 0; z < SPLIT_OUT; z++) {
            const float4* p = (const float4*)(g_part_c +
                ((size_t)z * DMODEL + m0 + ml) * BATCH + bq * 8);
            float4 v0 = p[0], v1 = p[1];
            s0.x += v0.x; s0.y += v0.y; s0.z += v0.z; s0.w += v0.w;
            s1.x += v1.x; s1.y += v1.y; s1.z += v1.z; s1.w += v1.w;
        }
        tile[ml][bq * 8 + 0] = s0.x; tile[ml][bq * 8 + 1] = s0.y;
        tile[ml][bq * 8 + 2] = s0.z; tile[ml][bq * 8 + 3] = s0.w;
        tile[ml][bq * 8 + 4] = s1.x; tile[ml][bq * 8 + 5] = s1.y;
        tile[ml][bq * 8 + 6] = s1.z; tile[ml][bq * 8 + 7] = s1.w;
    }
    __syncthreads();
    {
        int b = tid >> 3;         // 0..31
        int mq = tid & 7;         // 0..7  (8 m's)
        float4 o0 = make_float4(tile[mq * 8 + 0][b], tile[mq * 8 + 1][b],
                                tile[mq * 8 + 2][b], tile[mq * 8 + 3][b]);
        float4 o1 = make_float4(tile[mq * 8 + 4][b], tile[mq * 8 + 5][b],
                                tile[mq * 8 + 6][b], tile[mq * 8 + 7][b]);
        float* dst = out + (size_t)b * DMODEL + m0 + mq * 8;
        *(float4*)(dst) = o0;
        *(float4*)(dst + 4) = o1;
    }
}

// ===================================================================
extern "C" void kernel_launch(void* const* d_in, const int* in_sizes, int n_in,
                              void* d_out, int out_size) {
    const float* x    = (const float*)d_in[0];
    const float* cs   = (const float*)d_in[1];
    const float* cw   = (const float*)d_in[2];
    const float* cb   = (const float*)d_in[3];
    const float* Wssm = (const float*)d_in[4];
    const float* Wmlp = (const float*)d_in[5];
    const float* Wout = (const float*)d_in[6];
    const float* Wxp  = (const float*)d_in[7];
    const float* Wdt  = (const float*)d_in[8];
    const float* dtb  = (const float*)d_in[9];
    const float* Alog = (const float*)d_in[10];
    const float* Dv   = (const float*)d_in[11];
    const float* sst  = (const float*)d_in[12];
    float* out = (float*)d_out;

    transpose_x_kernel<<<DMODEL / 32, dim3(32, 8)>>>(x);
    gemm_in_kernel<<<dim3(DINNER / TROWS, 2, SPLIT_IN), 128>>>(Wssm, Wmlp);
    epi_a_kernel<<<DINNER / 128, 128>>>(cs, cw, cb);
    gemm_xp_kernel<<<dim3(1, 1, SPLIT_XP), 128>>>(Wxp);
    epi_b_kernel<<<(XDBDIM * BATCH) / 256, 256>>>();
    ssm_kernel<<<dim3(DINNER / 128, 8), 128>>>(Wdt, dtb, Alog, Dv, sst);
    gemm_out_kernel<<<dim3(DMODEL / TROWS, 1, SPLIT_OUT), 128>>>(Wout);
    epi_c_kernel<<<DMODEL / 64, 256>>>(out);
}

// round 7
// speedup vs baseline: 2.0186x; 1.4422x over previous
#include <cuda_runtime.h>
#include <cstdint>
#include <cstddef>

// Problem constants
#define BATCH   32
#define DMODEL  2560
#define DINNER  5120
#define NSTATE  16
#define DTRANK  160
#define XDBDIM  192          // DTRANK + 2*NSTATE

// Split-K configs
#define SPLIT_IN   4         // K=2560 -> 640 each   (grid 40*2*4 = 320)
#define SPLIT_XP   40        // K=5120 -> 128 each   (grid 2*40   = 80)
#define SPLIT_OUT  16        // K=5120 -> 320 each   (grid 20*16  = 320)

#define KCH   32             // k per pipeline chunk
#define KPAD  36             // padded smem row stride (floats)

// -------- scratch (static device globals; no allocation) ----------
__device__ __align__(256) float g_x32[BATCH * DMODEL];            // rna-tf32 x
__device__ __align__(256) float g_part_in[(2 * SPLIT_IN) * DINNER * BATCH];
__device__ __align__(256) float g_conv[BATCH * DINNER];           // rna-tf32
__device__ __align__(256) float g_g[BATCH * DINNER];
__device__ __align__(256) float g_part_b[SPLIT_XP * XDBDIM * BATCH];
__device__ __align__(256) float g_xdbT[XDBDIM * BATCH];
__device__ __align__(256) float g_z[BATCH * DINNER];              // rna-tf32
__device__ __align__(256) float g_part_c[SPLIT_OUT * DMODEL * BATCH];

// -------- helpers ----------
__device__ __forceinline__ uint32_t smem_u32(const void* p) {
    uint32_t r;
    asm("{.reg .u64 t; cvta.to.shared.u64 t, %1; cvt.u32.u64 %0, t;}"
        : "=r"(r) : "l"(p));
    return r;
}
__device__ __forceinline__ void cp_async16(uint32_t dst, const void* src) {
    asm volatile("cp.async.cg.shared.global [%0], [%1], 16;\n" ::"r"(dst), "l"(src));
}
__device__ __forceinline__ void cp_commit() {
    asm volatile("cp.async.commit_group;\n");
}
template <int N>
__device__ __forceinline__ void cp_wait() {
    asm volatile("cp.async.wait_group %0;\n" ::"n"(N));
}
__device__ __forceinline__ float silu_f(float v) {
    return v / (1.f + __expf(-v));
}
__device__ __forceinline__ float rn_tf32(float v) {
    uint32_t u;
    asm("cvt.rna.tf32.f32 %0, %1;" : "=r"(u) : "f"(v));
    return __uint_as_float(u);
}

// warp mma: D(16x8) += A(16x8,row) * B(8x8,col), tf32 inputs, f32 accum
__device__ __forceinline__ void mma_tf32(float* c, const uint32_t* a,
                                         const uint32_t* b) {
    asm volatile(
        "mma.sync.aligned.m16n8k8.row.col.f32.tf32.tf32.f32 "
        "{%0,%1,%2,%3}, {%4,%5,%6,%7}, {%8,%9}, {%0,%1,%2,%3};"
        : "+f"(c[0]), "+f"(c[1]), "+f"(c[2]), "+f"(c[3])
        : "r"(a[0]), "r"(a[1]), "r"(a[2]), "r"(a[3]), "r"(b[0]), "r"(b[1]));
}

// ===================================================================
// prep: round x to tf32-nearest (B operand of in-proj)
// ===================================================================
__global__ void __launch_bounds__(256) prep_x_kernel(const float* __restrict__ x) {
    int i = blockIdx.x * 256 + threadIdx.x;
    if (i < BATCH * DMODEL) g_x32[i] = rn_tf32(x[i]);
}

// ===================================================================
// Warp-MMA tf32 split-K GEMM: 128 threads, tile = 128 rows x 32 batch.
// A = W[row0..row0+127][k0..)   (smem, rows padded to KPAD)
// B = act[0..31][k0..)          (natural [batch][K] layout)
// Warp w: rows [row0+32w, row0+32w+32), 2 M-tiles x 4 N-tiles.
// Writes partial to part[d*32 + b].  klen multiple of KCH.
// ===================================================================
__device__ __forceinline__ void gemm_mma(const float* __restrict__ W,
                                         const float* __restrict__ Bm,
                                         float* __restrict__ part,
                                         int K, int k0, int klen, int row0) {
    __shared__ __align__(16) float w_s[2][128 * KPAD];   // 18 KB each
    __shared__ __align__(16) float x_s[2][32 * KPAD];    // 4.5 KB each

    const int tid = threadIdx.x;
    const int wid = tid >> 5;
    const int lane = tid & 31;
    const int gid = lane >> 2;    // 0..7
    const int t4 = lane & 3;      // 0..3

    const int nch = klen / KCH;

    const uint32_t ws_[2] = {smem_u32(&w_s[0][0]), smem_u32(&w_s[1][0])};
    const uint32_t xs_[2] = {smem_u32(&x_s[0][0]), smem_u32(&x_s[1][0])};

    auto fill = [&](int st, int c) {
        const int kc = k0 + c * KCH;
        uint32_t wd = ws_[st];
#pragma unroll
        for (int i = 0; i < 8; i++) {
            int p = tid + 128 * i;             // 0..1023
            int r = p >> 3, o = p & 7;
            cp_async16(wd + (uint32_t)(r * KPAD + o * 4) * 4,
                       W + (size_t)(row0 + r) * K + kc + o * 4);
        }
        uint32_t xd = xs_[st];
#pragma unroll
        for (int i = 0; i < 2; i++) {
            int p = tid + 128 * i;             // 0..255
            int r = p >> 3, o = p & 7;
            cp_async16(xd + (uint32_t)(r * KPAD + o * 4) * 4,
                       Bm + (size_t)r * K + kc + o * 4);
        }
        cp_commit();
    };

    fill(0, 0);
    if (nch > 1) fill(1, 1);

    float acc[2][4][4];
#pragma unroll
    for (int mt = 0; mt < 2; mt++)
#pragma unroll
        for (int nt = 0; nt < 4; nt++)
#pragma unroll
            for (int q = 0; q < 4; q++) acc[mt][nt][q] = 0.f;

    for (int c = 0; c < nch; c++) {
        if (c + 1 < nch) cp_wait<1>(); else cp_wait<0>();
        __syncthreads();
        const float* ws = w_s[c & 1];
        const float* xs = x_s[c & 1];
#pragma unroll
        for (int kstep = 0; kstep < KCH / 8; kstep++) {
            const int kk = kstep * 8;
            uint32_t a[2][4], b[4][2];
#pragma unroll
            for (int mt = 0; mt < 2; mt++) {
                int r0 = wid * 32 + mt * 16 + gid;
                a[mt][0] = __float_as_uint(ws[(r0)     * KPAD + kk + t4]);
                a[mt][1] = __float_as_uint(ws[(r0 + 8) * KPAD + kk + t4]);
                a[mt][2] = __float_as_uint(ws[(r0)     * KPAD + kk + t4 + 4]);
                a[mt][3] = __float_as_uint(ws[(r0 + 8) * KPAD + kk + t4 + 4]);
            }
#pragma unroll
            for (int nt = 0; nt < 4; nt++) {
                int n = nt * 8 + gid;
                b[nt][0] = __float_as_uint(xs[n * KPAD + kk + t4]);
                b[nt][1] = __float_as_uint(xs[n * KPAD + kk + t4 + 4]);
            }
#pragma unroll
            for (int mt = 0; mt < 2; mt++)
#pragma unroll
                for (int nt = 0; nt < 4; nt++)
                    mma_tf32(acc[mt][nt], a[mt], b[nt]);
        }
        __syncthreads();
        if (c + 2 < nch) fill(c & 1, c + 2);
    }

    // store: D[m][n] -> part[d*32 + b]
#pragma unroll
    for (int mt = 0; mt < 2; mt++) {
        int d0 = row0 + wid * 32 + mt * 16 + gid;
#pragma unroll
        for (int nt = 0; nt < 4; nt++) {
            int n = nt * 8 + 2 * t4;
            *(float2*)&part[(size_t)d0 * BATCH + n] =
                make_float2(acc[mt][nt][0], acc[mt][nt][1]);
            *(float2*)&part[(size_t)(d0 + 8) * BATCH + n] =
                make_float2(acc[mt][nt][2], acc[mt][nt][3]);
        }
    }
}

// ---- wrappers ----
__global__ void __launch_bounds__(128)
gemm_in_kernel(const float* __restrict__ Wssm, const float* __restrict__ Wmlp) {
    int sel = blockIdx.y, z = blockIdx.z;
    const float* W = sel ? Wmlp : Wssm;
    float* part = g_part_in + (size_t)(sel * SPLIT_IN + z) * DINNER * BATCH;
    gemm_mma(W, g_x32, part, DMODEL, z * (DMODEL / SPLIT_IN),
             DMODEL / SPLIT_IN, blockIdx.x * 128);
}

__global__ void __launch_bounds__(128)
gemm_xp_kernel(const float* __restrict__ Wxp) {
    int z = blockIdx.z;
    float* part = g_part_b + (size_t)z * XDBDIM * BATCH;
    // M=192: blocks cover rows [0,128) and [64,192); overlap writes identical
    gemm_mma(Wxp, g_conv, part, DINNER, z * (DINNER / SPLIT_XP),
             DINNER / SPLIT_XP, blockIdx.x * 64);
}

__global__ void __launch_bounds__(128)
gemm_out_kernel(const float* __restrict__ Wout) {
    int z = blockIdx.z;
    float* part = g_part_c + (size_t)z * DMODEL * BATCH;
    gemm_mma(Wout, g_z, part, DINNER, z * (DINNER / SPLIT_OUT),
             DINNER / SPLIT_OUT, blockIdx.x * 128);
}

// ===================================================================
// Epilogue A: sum in_proj partials [z][d][b], conv + SiLU -> g_conv[b][d]
//             (tf32-rounded), gate SiLU -> g_g[b][d]
// ===================================================================
__global__ void __launch_bounds__(128)
epi_a_kernel(const float* __restrict__ conv_states,
             const float* __restrict__ conv_w,
             const float* __restrict__ conv_b) {
    int d = blockIdx.x * 128 + threadIdx.x;
    float xs[BATCH], res[BATCH];
#pragma unroll
    for (int b = 0; b < BATCH; b++) { xs[b] = 0.f; res[b] = 0.f; }
#pragma unroll
    for (int z = 0; z < SPLIT_IN; z++) {
        const float4* p = (const float4*)(g_part_in + ((size_t)z * DINNER + d) * BATCH);
#pragma unroll
        for (int q = 0; q < 8; q++) {
            float4 v = p[q];
            xs[q * 4 + 0] += v.x; xs[q * 4 + 1] += v.y;
            xs[q * 4 + 2] += v.z; xs[q * 4 + 3] += v.w;
        }
    }
#pragma unroll
    for (int z = SPLIT_IN; z < 2 * SPLIT_IN; z++) {
        const float4* p = (const float4*)(g_part_in + ((size_t)z * DINNER + d) * BATCH);
#pragma unroll
        for (int q = 0; q < 8; q++) {
            float4 v = p[q];
            res[q * 4 + 0] += v.x; res[q * 4 + 1] += v.y;
            res[q * 4 + 2] += v.z; res[q * 4 + 3] += v.w;
        }
    }

    float cw0 = conv_w[d];
    float cw1 = conv_w[DINNER + d];
    float cw2 = conv_w[2 * DINNER + d];
    float cw3 = conv_w[3 * DINNER + d];
    float cb = conv_b[d];

#pragma unroll
    for (int b = 0; b < BATCH; b++) {
        float conv = conv_states[(size_t)(1 * BATCH + b) * DINNER + d] * cw0
                   + conv_states[(size_t)(2 * BATCH + b) * DINNER + d] * cw1
                   + conv_states[(size_t)(3 * BATCH + b) * DINNER + d] * cw2
                   + xs[b] * cw3 + cb;
        g_conv[(size_t)b * DINNER + d] = rn_tf32(silu_f(conv));
        g_g[(size_t)b * DINNER + d] = silu_f(res[b]);
    }
}

// ===================================================================
// Epilogue B: sum x_proj partials [z][r][b] -> g_xdbT[r][b]
// ===================================================================
__global__ void __launch_bounds__(256) epi_b_kernel() {
    int t = blockIdx.x * 256 + threadIdx.x;   // r*32+b
    float s = 0.f;
#pragma unroll 8
    for (int z = 0; z < SPLIT_XP; z++)
        s += g_part_b[(size_t)z * XDBDIM * BATCH + t];
    g_xdbT[t] = s;
}

// ===================================================================
// SSM kernel: dt GEMV + softplus + state scan + gate -> g_z[b][d] (tf32)
// grid (DINNER/128, 8), block 128; blockIdx.y = 4-batch group
// ===================================================================
#define SSM_BB 4
__global__ void __launch_bounds__(128)
ssm_kernel(const float* __restrict__ W_dt, const float* __restrict__ dt_bias,
           const float* __restrict__ A_log, const float* __restrict__ Dv,
           const float* __restrict__ ssm_state) {
    __shared__ float xdb_s[XDBDIM * SSM_BB];
    const int by = blockIdx.y;
    for (int u = threadIdx.x; u < XDBDIM * SSM_BB; u += 128) {
        int r = u >> 2, bb = u & 3;
        xdb_s[u] = g_xdbT[(size_t)r * BATCH + by * SSM_BB + bb];
    }
    __syncthreads();

    const int d = blockIdx.x * 128 + threadIdx.x;

    float accdt[SSM_BB];
#pragma unroll
    for (int bb = 0; bb < SSM_BB; bb++) accdt[bb] = 0.f;

    const float4* wd = (const float4*)(W_dt + (size_t)d * DTRANK);
#pragma unroll 10
    for (int r4 = 0; r4 < DTRANK / 4; r4++) {
        float4 w = wd[r4];
        float wa[4] = {w.x, w.y, w.z, w.w};
#pragma unroll
        for (int j = 0; j < 4; j++) {
            float4 xv = *(const float4*)&xdb_s[(r4 * 4 + j) * SSM_BB];
            accdt[0] += wa[j] * xv.x;
            accdt[1] += wa[j] * xv.y;
            accdt[2] += wa[j] * xv.z;
            accdt[3] += wa[j] * xv.w;
        }
    }

    float a[NSTATE];
    const float4* al = (const float4*)(A_log + (size_t)d * NSTATE);
#pragma unroll
    for (int n4 = 0; n4 < 4; n4++) {
        float4 v = al[n4];
        a[n4 * 4 + 0] = -__expf(v.x);
        a[n4 * 4 + 1] = -__expf(v.y);
        a[n4 * 4 + 2] = -__expf(v.z);
        a[n4 * 4 + 3] = -__expf(v.w);
    }
    float Dd = Dv[d];
    float bias = dt_bias[d];

#pragma unroll
    for (int bb = 0; bb < SSM_BB; bb++) {
        int b = by * SSM_BB + bb;
        float dtv = accdt[bb] + bias;
        float dt = dtv > 20.f ? dtv : log1pf(__expf(dtv));
        float c = g_conv[(size_t)b * DINNER + d];
        float gv = g_g[(size_t)b * DINNER + d];
        float y = Dd * c;
        const float4* s4 =
            (const float4*)(ssm_state + ((size_t)b * DINNER + d) * NSTATE);
#pragma unroll
        for (int n4 = 0; n4 < 4; n4++) {
            float4 s = s4[n4];
            float sa[4] = {s.x, s.y, s.z, s.w};
#pragma unroll
            for (int h = 0; h < 4; h++) {
                int n = n4 * 4 + h;
                float dA = __expf(dt * a[n]);
                float hv = sa[h] * dA + dt * xdb_s[(DTRANK + n) * SSM_BB + bb] * c;
                y += hv * xdb_s[(DTRANK + NSTATE + n) * SSM_BB + bb];
            }
        }
        g_z[(size_t)b * DINNER + d] = rn_tf32(y * gv);
    }
}

// ===================================================================
// Epilogue C: sum out_proj partials [z][m][b] -> out (B, DMODEL)
// ===================================================================
__global__ void __launch_bounds__(256) epi_c_kernel(float* __restrict__ out) {
    __shared__ float tile[64][33];
    int m0 = blockIdx.x * 64;
    int tid = threadIdx.x;
    {
        int ml = tid >> 2;        // 0..63
        int bq = tid & 3;         // 0..3 (8 b's)
        float4 s0 = make_float4(0.f, 0.f, 0.f, 0.f);
        float4 s1 = make_float4(0.f, 0.f, 0.f, 0.f);
#pragma unroll
        for (int z = 0; z < SPLIT_OUT; z++) {
            const float4* p = (const float4*)(g_part_c +
                ((size_t)z * DMODEL + m0 + ml) * BATCH + bq * 8);
            float4 v0 = p[0], v1 = p[1];
            s0.x += v0.x; s0.y += v0.y; s0.z += v0.z; s0.w += v0.w;
            s1.x += v1.x; s1.y += v1.y; s1.z += v1.z; s1.w += v1.w;
        }
        tile[ml][bq * 8 + 0] = s0.x; tile[ml][bq * 8 + 1] = s0.y;
        tile[ml][bq * 8 + 2] = s0.z; tile[ml][bq * 8 + 3] = s0.w;
        tile[ml][bq * 8 + 4] = s1.x; tile[ml][bq * 8 + 5] = s1.y;
        tile[ml][bq * 8 + 6] = s1.z; tile[ml][bq * 8 + 7] = s1.w;
    }
    __syncthreads();
    {
        int b = tid >> 3;         // 0..31
        int mq = tid & 7;         // 0..7
        float4 o0 = make_float4(tile[mq * 8 + 0][b], tile[mq * 8 + 1][b],
                                tile[mq * 8 + 2][b], tile[mq * 8 + 3][b]);
        float4 o1 = make_float4(tile[mq * 8 + 4][b], tile[mq * 8 + 5][b],
                                tile[mq * 8 + 6][b], tile[mq * 8 + 7][b]);
        float* dst = out + (size_t)b * DMODEL + m0 + mq * 8;
        *(float4*)(dst) = o0;
        *(float4*)(dst + 4) = o1;
    }
}

// ===================================================================
extern "C" void kernel_launch(void* const* d_in, const int* in_sizes, int n_in,
                              void* d_out, int out_size) {
    const float* x    = (const float*)d_in[0];
    const float* cs   = (const float*)d_in[1];
    const float* cw   = (const float*)d_in[2];
    const float* cb   = (const float*)d_in[3];
    const float* Wssm = (const float*)d_in[4];
    const float* Wmlp = (const float*)d_in[5];
    const float* Wout = (const float*)d_in[6];
    const float* Wxp  = (const float*)d_in[7];
    const float* Wdt  = (const float*)d_in[8];
    const float* dtb  = (const float*)d_in[9];
    const float* Alog = (const float*)d_in[10];
    const float* Dv   = (const float*)d_in[11];
    const float* sst  = (const float*)d_in[12];
    float* out = (float*)d_out;

    prep_x_kernel<<<(BATCH * DMODEL + 255) / 256, 256>>>(x);
    gemm_in_kernel<<<dim3(DINNER / 128, 2, SPLIT_IN), 128>>>(Wssm, Wmlp);
    epi_a_kernel<<<DINNER / 128, 128>>>(cs, cw, cb);
    gemm_xp_kernel<<<dim3(2, 1, SPLIT_XP), 128>>>(Wxp);
    epi_b_kernel<<<(XDBDIM * BATCH) / 256, 256>>>();
    ssm_kernel<<<dim3(DINNER / 128, 8), 128>>>(Wdt, dtb, Alog, Dv, sst);
    gemm_out_kernel<<<dim3(DMODEL / 128, 1, SPLIT_OUT), 128>>>(Wout);
    epi_c_kernel<<<DMODEL / 64, 256>>>(out);
}